// round 11
// baseline (speedup 1.0000x reference)
#include <cuda_runtime.h>
#include <cuda_bf16.h>
#include <cstdint>
#include <math.h>

#define HID 1024
#define NHEAD 16
#define HDIM 64
#define BATCH 2
#define SEQ 2048
#define M_TOT (BATCH * SEQ)     // 4096
#define N_QKV (3 * HID)         // 3072
#define K3 (3 * HID)            // augmented K for bf16x3 split

// ---------------------------------------------------------------------------
// Scratch
// ---------------------------------------------------------------------------
__device__ __nv_bfloat16 g_qkvh[(size_t)M_TOT * N_QKV];     // 24 MB
__device__ __nv_bfloat16 g_qkvl[(size_t)M_TOT * N_QKV];     // 24 MB
__device__ __nv_bfloat16 g_xs[(size_t)M_TOT * K3];          // 24 MB
__device__ __nv_bfloat16 g_wqkvs[(size_t)N_QKV * K3];       // 18 MB
__device__ __nv_bfloat16 g_atts[(size_t)M_TOT * K3];        // 24 MB
__device__ __nv_bfloat16 g_wouts[(size_t)HID * K3];         // 6 MB

// ---------------------------------------------------------------------------
// Helpers
// ---------------------------------------------------------------------------
__device__ __forceinline__ uint32_t smem_u32(const void* p) {
    uint32_t a;
    asm("{ .reg .u64 t; cvta.to.shared.u64 t, %1; cvt.u32.u64 %0, t; }"
        : "=r"(a) : "l"(p));
    return a;
}
__device__ __forceinline__ void cp16(uint32_t dst, const void* src) {
    asm volatile("cp.async.cg.shared.global [%0], [%1], 16;" :: "r"(dst), "l"(src));
}
__device__ __forceinline__ void cp_commit() { asm volatile("cp.async.commit_group;"); }
template <int N>
__device__ __forceinline__ void cp_wait() { asm volatile("cp.async.wait_group %0;" :: "n"(N)); }

__device__ __forceinline__ void ldm_x4(uint32_t addr, uint32_t& r0, uint32_t& r1,
                                       uint32_t& r2, uint32_t& r3) {
    asm volatile("ldmatrix.sync.aligned.m8n8.x4.shared.b16 {%0,%1,%2,%3}, [%4];"
                 : "=r"(r0), "=r"(r1), "=r"(r2), "=r"(r3) : "r"(addr));
}
__device__ __forceinline__ void ldm_x4_t(uint32_t addr, uint32_t& r0, uint32_t& r1,
                                         uint32_t& r2, uint32_t& r3) {
    asm volatile("ldmatrix.sync.aligned.m8n8.x4.trans.shared.b16 {%0,%1,%2,%3}, [%4];"
                 : "=r"(r0), "=r"(r1), "=r"(r2), "=r"(r3) : "r"(addr));
}
__device__ __forceinline__ void mma_bf16(float* c, const uint32_t* a,
                                         uint32_t b0, uint32_t b1) {
    asm volatile(
        "mma.sync.aligned.m16n8k16.row.col.f32.bf16.bf16.f32 "
        "{%0,%1,%2,%3}, {%4,%5,%6,%7}, {%8,%9}, {%0,%1,%2,%3};"
        : "+f"(c[0]), "+f"(c[1]), "+f"(c[2]), "+f"(c[3])
        : "r"(a[0]), "r"(a[1]), "r"(a[2]), "r"(a[3]), "r"(b0), "r"(b1));
}
__device__ __forceinline__ uint32_t packbf(float a, float b) {
    __nv_bfloat162 t = __floats2bfloat162_rn(a, b);
    return *(uint32_t*)&t;
}
__device__ __forceinline__ uint32_t mulbf2(uint32_t x, uint32_t s) {
    __nv_bfloat162 r = __hmul2(*(__nv_bfloat162*)&x, *(__nv_bfloat162*)&s);
    return *(uint32_t*)&r;
}

// ---------------------------------------------------------------------------
// Split fp32 -> bf16 hi/lo augmented. mode0: [hi|hi|lo], mode1: [hi|lo|hi]
// ---------------------------------------------------------------------------
__global__ void __launch_bounds__(256) split_bf16(
    const float* __restrict__ in, __nv_bfloat16* __restrict__ out,
    int R, int K, int mode)
{
    const int half = K >> 1;
    const int total = R * half;
    for (int i = blockIdx.x * blockDim.x + threadIdx.x; i < total;
         i += gridDim.x * blockDim.x) {
        int r = i / half;
        int k2 = (i - r * half) * 2;
        float2 x = *(const float2*)(in + (size_t)r * K + k2);
        __nv_bfloat16 h0 = __float2bfloat16(x.x);
        __nv_bfloat16 h1 = __float2bfloat16(x.y);
        __nv_bfloat16 l0 = __float2bfloat16(x.x - __bfloat162float(h0));
        __nv_bfloat16 l1 = __float2bfloat16(x.y - __bfloat162float(h1));
        __nv_bfloat162 hh, ll;
        hh.x = h0; hh.y = h1;
        ll.x = l0; ll.y = l1;
        __nv_bfloat162* o = (__nv_bfloat162*)(out + (size_t)r * (3 * K) + k2);
        const int KH = K >> 1;
        if (mode == 0) { o[0] = hh; o[KH] = hh; o[2 * KH] = ll; }
        else           { o[0] = hh; o[KH] = ll; o[2 * KH] = hh; }
    }
}

// ---------------------------------------------------------------------------
// HMMA bf16 NT GEMM: 128x128 CTA tile, 8 warps @ 64x32, BK=64, 3-stage
// cp.async pipeline, ping-pong fragment buffers, 1 sync per BK=64. (R9)
// ---------------------------------------------------------------------------
#define GBM 128
#define GBN 128
#define GBK 64
#define LDSK 72
#define GSTAGES 3
#define STG_A (GBM * LDSK * 2)             // 18432 B
#define STG_PAIR (STG_A * 2)               // 36864 B
#define GEMM_SMEM (GSTAGES * STG_PAIR)     // 110592 B

template <bool BF16OUT>
__global__ void __launch_bounds__(256, 2) gemm_hmma(
    const __nv_bfloat16* __restrict__ A, const __nv_bfloat16* __restrict__ B,
    const float* __restrict__ bias, float* __restrict__ C,
    __nv_bfloat16* __restrict__ Ch, __nv_bfloat16* __restrict__ Cl,
    int M, int N, int K)
{
    extern __shared__ char gsm[];
    const uint32_t sbase = smem_u32(gsm);

    const int tid = threadIdx.x;
    const int wid = tid >> 5;
    const int lane = tid & 31;
    const int warp_m = (wid & 1) * 64;
    const int warp_n = (wid >> 1) * 32;
    const int m0 = blockIdx.y * GBM;
    const int n0 = blockIdx.x * GBN;

    const int ld_row = tid >> 3;       // 0..31
    const int ld_ch = (tid & 7) * 8;   // 0..56

    float acc[4][4][4];
#pragma unroll
    for (int i = 0; i < 4; i++)
#pragma unroll
        for (int j = 0; j < 4; j++)
#pragma unroll
            for (int q = 0; q < 4; q++) acc[i][j][q] = 0.f;

    const int NS = K / GBK;

    auto load_stage = [&](int s, int p) {
        const int k0 = s * GBK;
        const uint32_t base = sbase + (uint32_t)p * STG_PAIR;
#pragma unroll
        for (int t = 0; t < 4; t++) {
            int row = ld_row + t * 32;
            uint32_t doff = (uint32_t)((row * LDSK + ld_ch) * 2);
            cp16(base + doff,         A + (size_t)(m0 + row) * K + k0 + ld_ch);
            cp16(base + STG_A + doff, B + (size_t)(n0 + row) * K + k0 + ld_ch);
        }
    };

    const int a_row = warp_m + (lane & 15);
    const int b_row = warp_n + (lane & 15);
    const int k_half = (lane >> 4) * 8;

    auto load_frags = [&](int p, int kk, uint32_t (&af)[4][4], uint32_t (&bf)[2][4]) {
        const uint32_t aBase = sbase + (uint32_t)p * STG_PAIR;
        const uint32_t bBase = aBase + STG_A;
        const int kc = kk * 16 + k_half;
#pragma unroll
        for (int i = 0; i < 4; i++) {
            uint32_t addr = aBase + (uint32_t)(((a_row + i * 16) * LDSK + kc) * 2);
            ldm_x4(addr, af[i][0], af[i][1], af[i][2], af[i][3]);
        }
#pragma unroll
        for (int jp = 0; jp < 2; jp++) {
            uint32_t addr = bBase + (uint32_t)(((b_row + jp * 16) * LDSK + kc) * 2);
            ldm_x4(addr, bf[jp][0], bf[jp][1], bf[jp][2], bf[jp][3]);
        }
    };

    auto mma_all = [&](uint32_t (&af)[4][4], uint32_t (&bf)[2][4]) {
#pragma unroll
        for (int i = 0; i < 4; i++) {
#pragma unroll
            for (int jp = 0; jp < 2; jp++) {
                mma_bf16(acc[i][2 * jp],     af[i], bf[jp][0], bf[jp][2]);
                mma_bf16(acc[i][2 * jp + 1], af[i], bf[jp][1], bf[jp][3]);
            }
        }
    };

    // Prologue: 2 stages in flight
    load_stage(0, 0); cp_commit();
    load_stage(1, 1); cp_commit();
    cp_wait<1>();
    __syncthreads();

    uint32_t afA[4][4], bfA[2][4], afB[4][4], bfB[2][4];
    load_frags(0, 0, afA, bfA);

    int p = 0, pn = 2;
    for (int s = 0; s < NS; s++) {
        { int ns = s + 2; if (ns < NS) load_stage(ns, pn); cp_commit(); }

        load_frags(p, 1, afB, bfB); mma_all(afA, bfA);
        load_frags(p, 2, afA, bfA); mma_all(afB, bfB);
        load_frags(p, 3, afB, bfB); mma_all(afA, bfA);
        mma_all(afB, bfB);

        cp_wait<1>();
        __syncthreads();
        p  = (p == 2)  ? 0 : p + 1;
        pn = (pn == 2) ? 0 : pn + 1;
        if (s + 1 < NS) load_frags(p, 0, afA, bfA);
    }

    const int row_g = lane >> 2;
    const int col_g = (lane & 3) * 2;
#pragma unroll
    for (int i = 0; i < 4; i++) {
#pragma unroll
        for (int j = 0; j < 4; j++) {
            int row = m0 + warp_m + i * 16 + row_g;
            int col = n0 + warp_n + j * 8 + col_g;
            float b0 = bias[col], b1 = bias[col + 1];
            float v00 = acc[i][j][0] + b0, v01 = acc[i][j][1] + b1;
            float v10 = acc[i][j][2] + b0, v11 = acc[i][j][3] + b1;
            if (BF16OUT) {
                __nv_bfloat162 h0 = __floats2bfloat162_rn(v00, v01);
                __nv_bfloat162 h1 = __floats2bfloat162_rn(v10, v11);
                __nv_bfloat162 l0 = __floats2bfloat162_rn(
                    v00 - __bfloat162float(h0.x), v01 - __bfloat162float(h0.y));
                __nv_bfloat162 l1 = __floats2bfloat162_rn(
                    v10 - __bfloat162float(h1.x), v11 - __bfloat162float(h1.y));
                *(__nv_bfloat162*)(Ch + (size_t)row * N + col) = h0;
                *(__nv_bfloat162*)(Ch + (size_t)(row + 8) * N + col) = h1;
                *(__nv_bfloat162*)(Cl + (size_t)row * N + col) = l0;
                *(__nv_bfloat162*)(Cl + (size_t)(row + 8) * N + col) = l1;
            } else {
                *(float2*)(C + (size_t)row * N + col) = make_float2(v00, v01);
                *(float2*)(C + (size_t)(row + 8) * N + col) = make_float2(v10, v11);
            }
        }
    }
}

// ---------------------------------------------------------------------------
// Tensor-core flash attention, bf16x3 split, fp32 accumulate.
// R11: CTA = 128 q-rows (8 warps x 16 rows, 256 threads) -> K/V gmem traffic
// and per-tile pipeline overhead halved. Max-free softmax (R10).
// ---------------------------------------------------------------------------
#define APITCH 72
#define QROWS 128
#define QTILE (QROWS * APITCH)
#define KTILE (64 * APITCH)
#define ATT_SMEM ((2 * QTILE + 2 * 4 * KTILE) * 2)   // 110592 B

__global__ void __launch_bounds__(256) attn_tc(
    const __nv_bfloat16* __restrict__ qh, const __nv_bfloat16* __restrict__ ql,
    __nv_bfloat16* __restrict__ atts)
{
    extern __shared__ __nv_bfloat16 sm[];
    __nv_bfloat16* Qh = sm;
    __nv_bfloat16* Ql = Qh + QTILE;
    __nv_bfloat16* KV = Ql + QTILE;      // stage p: [Kh, Kl, Vh, Vl] each KTILE

    const int tid = threadIdx.x;
    const int wid = tid >> 5;
    const int lane = tid & 31;
    const int bh = blockIdx.y;
    const int b = bh >> 4, h = bh & 15;
    const int q0 = blockIdx.x * QROWS;
    const size_t tokbase = (size_t)b * SEQ;

    const uint32_t sQh = smem_u32(Qh), sQl = smem_u32(Ql);
    const uint32_t sKV = smem_u32(KV);

    // Load Q tile (hi, lo): 128 rows x 64 cols
    {
        const size_t qoff = (tokbase + q0) * N_QKV + h * HDIM;
#pragma unroll
        for (int t = 0; t < 4; t++) {
            int idx = tid + t * 256;       // 0..1023
            int row = idx >> 3;            // 0..127
            int ch = (idx & 7) * 8;
            *(uint4*)(Qh + row * APITCH + ch) = *(const uint4*)(qh + qoff + (size_t)row * N_QKV + ch);
            *(uint4*)(Ql + row * APITCH + ch) = *(const uint4*)(ql + qoff + (size_t)row * N_QKV + ch);
        }
    }

    auto load_kv = [&](int kt, int p) {
        const size_t koff = (tokbase + kt * 64) * N_QKV + HID + h * HDIM;
        const size_t voff = koff + HID;
        const uint32_t base = sKV + (uint32_t)p * (4 * KTILE * 2);
#pragma unroll
        for (int t = 0; t < 2; t++) {
            int idx = tid + t * 256;       // 0..511
            int row = idx >> 3;            // 0..63
            int ch = (idx & 7) * 8;
            size_t g = (size_t)row * N_QKV + ch;
            uint32_t doff = (uint32_t)((row * APITCH + ch) * 2);
            cp16(base + doff,                 qh + koff + g);
            cp16(base + KTILE * 2 + doff,     ql + koff + g);
            cp16(base + 2 * KTILE * 2 + doff, qh + voff + g);
            cp16(base + 3 * KTILE * 2 + doff, ql + voff + g);
        }
    };

    load_kv(0, 0);
    cp_commit();
    __syncthreads();   // Q stores visible

    const int lrow = lane & 15;
    const int lkh = (lane >> 4) * 8;
    const int vkey = (lane >> 4) * 8 + (lane & 7);
    const int vd = ((lane >> 3) & 1) * 8;

    // Hoist Q fragments (hi, lo), pre-scaled by 1/8 (exact in bf16)
    const uint32_t SC = 0x3E003E00u;   // (0.125, 0.125) bf16x2
    uint32_t qfh[4][4], qfl[4][4];
#pragma unroll
    for (int kk = 0; kk < 4; kk++) {
        const uint32_t qoff2 = (uint32_t)(((wid * 16 + lrow) * APITCH + kk * 16 + lkh) * 2);
        ldm_x4(sQh + qoff2, qfh[kk][0], qfh[kk][1], qfh[kk][2], qfh[kk][3]);
        ldm_x4(sQl + qoff2, qfl[kk][0], qfl[kk][1], qfl[kk][2], qfl[kk][3]);
#pragma unroll
        for (int r = 0; r < 4; r++) {
            qfh[kk][r] = mulbf2(qfh[kk][r], SC);
            qfl[kk][r] = mulbf2(qfl[kk][r], SC);
        }
    }

    float l0 = 0.f, l1 = 0.f;
    float o[8][4];
#pragma unroll
    for (int t = 0; t < 8; t++)
#pragma unroll
        for (int q = 0; q < 4; q++) o[t][q] = 0.f;

    const int NK = SEQ / 64;
    for (int kt = 0; kt < NK; kt++) {
        const int p = kt & 1;
        cp_wait<0>();
        __syncthreads();
        if (kt + 1 < NK) load_kv(kt + 1, p ^ 1);
        cp_commit();

        const uint32_t base = sKV + (uint32_t)p * (4 * KTILE * 2);
        const uint32_t sKh = base;
        const uint32_t sKl = base + KTILE * 2;
        const uint32_t sVh = base + 2 * KTILE * 2;
        const uint32_t sVl = base + 3 * KTILE * 2;

        auto load_kfrags = [&](int kk, uint32_t (&kh)[4][4], uint32_t (&kl)[4][4]) {
#pragma unroll
            for (int jp = 0; jp < 4; jp++) {
                const uint32_t koff2 = (uint32_t)(((jp * 16 + lrow) * APITCH + kk * 16 + lkh) * 2);
                ldm_x4(sKh + koff2, kh[jp][0], kh[jp][1], kh[jp][2], kh[jp][3]);
                ldm_x4(sKl + koff2, kl[jp][0], kl[jp][1], kl[jp][2], kl[jp][3]);
            }
        };
        auto load_vfrags = [&](int kk, uint32_t (&vh)[4][4], uint32_t (&vl)[4][4]) {
#pragma unroll
            for (int dt = 0; dt < 4; dt++) {
                const uint32_t voff2 = (uint32_t)(((kk * 16 + vkey) * APITCH + dt * 16 + vd) * 2);
                ldm_x4_t(sVh + voff2, vh[dt][0], vh[dt][1], vh[dt][2], vh[dt][3]);
                ldm_x4_t(sVl + voff2, vl[dt][0], vl[dt][1], vl[dt][2], vl[dt][3]);
            }
        };

        // ---- S = Q K^T (3-term split); grouped by term, frag ping-pong ----
        float sf[8][4];
#pragma unroll
        for (int t = 0; t < 8; t++)
#pragma unroll
            for (int q = 0; q < 4; q++) sf[t][q] = 0.f;

        auto s_mma = [&](int kk, uint32_t (&kh)[4][4], uint32_t (&kl)[4][4]) {
#pragma unroll
            for (int jp = 0; jp < 4; jp++) {
                mma_bf16(sf[2 * jp],     qfh[kk], kh[jp][0], kh[jp][2]);
                mma_bf16(sf[2 * jp + 1], qfh[kk], kh[jp][1], kh[jp][3]);
            }
#pragma unroll
            for (int jp = 0; jp < 4; jp++) {
                mma_bf16(sf[2 * jp],     qfh[kk], kl[jp][0], kl[jp][2]);
                mma_bf16(sf[2 * jp + 1], qfh[kk], kl[jp][1], kl[jp][3]);
            }
#pragma unroll
            for (int jp = 0; jp < 4; jp++) {
                mma_bf16(sf[2 * jp],     qfl[kk], kh[jp][0], kh[jp][2]);
                mma_bf16(sf[2 * jp + 1], qfl[kk], kh[jp][1], kh[jp][3]);
            }
        };

        {
            uint32_t khA[4][4], klA[4][4], khB[4][4], klB[4][4];
            load_kfrags(0, khA, klA);
            load_kfrags(1, khB, klB); s_mma(0, khA, klA);
            load_kfrags(2, khA, klA); s_mma(1, khB, klB);
            load_kfrags(3, khB, klB); s_mma(2, khA, klA);
            s_mma(3, khB, klB);
        }

        // ---- V(kk=0) frags issued before exp to hide LDSM latency ----
        uint32_t vhA[4][4], vlA[4][4], vhB[4][4], vlB[4][4];
        load_vfrags(0, vhA, vlA);

        // ---- max-free softmax: P = exp(S), accumulate row sums per lane ----
#pragma unroll
        for (int t = 0; t < 8; t++) {
            sf[t][0] = __expf(sf[t][0]);
            sf[t][1] = __expf(sf[t][1]);
            sf[t][2] = __expf(sf[t][2]);
            sf[t][3] = __expf(sf[t][3]);
            l0 += sf[t][0] + sf[t][1];
            l1 += sf[t][2] + sf[t][3];
        }

        // ---- pack P into A-operand frags (hi + lo) ----
        uint32_t ph[4][4], pl[4][4];
#pragma unroll
        for (int kk = 0; kk < 4; kk++) {
            float* c0 = sf[2 * kk];
            float* c1 = sf[2 * kk + 1];
            ph[kk][0] = packbf(c0[0], c0[1]);
            ph[kk][1] = packbf(c0[2], c0[3]);
            ph[kk][2] = packbf(c1[0], c1[1]);
            ph[kk][3] = packbf(c1[2], c1[3]);
            __nv_bfloat162* hp;
            hp = (__nv_bfloat162*)&ph[kk][0];
            pl[kk][0] = packbf(c0[0] - __bfloat162float(hp->x), c0[1] - __bfloat162float(hp->y));
            hp = (__nv_bfloat162*)&ph[kk][1];
            pl[kk][1] = packbf(c0[2] - __bfloat162float(hp->x), c0[3] - __bfloat162float(hp->y));
            hp = (__nv_bfloat162*)&ph[kk][2];
            pl[kk][2] = packbf(c1[0] - __bfloat162float(hp->x), c1[1] - __bfloat162float(hp->y));
            hp = (__nv_bfloat162*)&ph[kk][3];
            pl[kk][3] = packbf(c1[2] - __bfloat162float(hp->x), c1[3] - __bfloat162float(hp->y));
        }

        // ---- O += P V (3-term split); grouped by term, frag ping-pong ----
        auto pv_mma = [&](int kk, uint32_t (&vh)[4][4], uint32_t (&vl)[4][4]) {
#pragma unroll
            for (int dt = 0; dt < 4; dt++) {
                mma_bf16(o[2 * dt],     ph[kk], vh[dt][0], vh[dt][2]);
                mma_bf16(o[2 * dt + 1], ph[kk], vh[dt][1], vh[dt][3]);
            }
#pragma unroll
            for (int dt = 0; dt < 4; dt++) {
                mma_bf16(o[2 * dt],     ph[kk], vl[dt][0], vl[dt][2]);
                mma_bf16(o[2 * dt + 1], ph[kk], vl[dt][1], vl[dt][3]);
            }
#pragma unroll
            for (int dt = 0; dt < 4; dt++) {
                mma_bf16(o[2 * dt],     pl[kk], vh[dt][0], vh[dt][2]);
                mma_bf16(o[2 * dt + 1], pl[kk], vh[dt][1], vh[dt][3]);
            }
        };

        load_vfrags(1, vhB, vlB); pv_mma(0, vhA, vlA);
        load_vfrags(2, vhA, vlA); pv_mma(1, vhB, vlB);
        load_vfrags(3, vhB, vlB); pv_mma(2, vhA, vlA);
        pv_mma(3, vhB, vlB);
    }

    // ---- one-time cross-lane row-sum reduction (quad lanes share a row) ----
    l0 += __shfl_xor_sync(0xffffffffu, l0, 1);
    l0 += __shfl_xor_sync(0xffffffffu, l0, 2);
    l1 += __shfl_xor_sync(0xffffffffu, l1, 1);
    l1 += __shfl_xor_sync(0xffffffffu, l1, 2);

    // ---- epilogue: write augmented [hi|hi|lo] rows for GEMM2 ----
    const float inv0 = 1.f / l0, inv1 = 1.f / l1;
    const int gr0 = q0 + wid * 16 + (lane >> 2);
    const int gr1 = gr0 + 8;
    const size_t r0base = (tokbase + gr0) * (size_t)K3;
    const size_t r1base = (tokbase + gr1) * (size_t)K3;
#pragma unroll
    for (int t = 0; t < 8; t++) {
        int col = h * HDIM + t * 8 + (lane & 3) * 2;
        float v00 = o[t][0] * inv0, v01 = o[t][1] * inv0;
        float v10 = o[t][2] * inv1, v11 = o[t][3] * inv1;
        __nv_bfloat162 h0 = __floats2bfloat162_rn(v00, v01);
        __nv_bfloat162 h1 = __floats2bfloat162_rn(v10, v11);
        __nv_bfloat162 lo0 = __floats2bfloat162_rn(v00 - __bfloat162float(h0.x),
                                                   v01 - __bfloat162float(h0.y));
        __nv_bfloat162 lo1 = __floats2bfloat162_rn(v10 - __bfloat162float(h1.x),
                                                   v11 - __bfloat162float(h1.y));
        *(__nv_bfloat162*)(atts + r0base + col) = h0;
        *(__nv_bfloat162*)(atts + r0base + HID + col) = h0;
        *(__nv_bfloat162*)(atts + r0base + 2 * HID + col) = lo0;
        *(__nv_bfloat162*)(atts + r1base + col) = h1;
        *(__nv_bfloat162*)(atts + r1base + HID + col) = h1;
        *(__nv_bfloat162*)(atts + r1base + 2 * HID + col) = lo1;
    }
}

// ---------------------------------------------------------------------------
// Launch
// ---------------------------------------------------------------------------
extern "C" void kernel_launch(void* const* d_in, const int* in_sizes, int n_in,
                              void* d_out, int out_size)
{
    const float *x = nullptr, *w_qkv = nullptr, *b_qkv = nullptr,
                *w_out = nullptr, *b_out = nullptr;
    for (int i = 0; i < n_in; i++) {
        const float* p = (const float*)d_in[i];
        switch (in_sizes[i]) {
            case M_TOT * HID: x = p; break;
            case N_QKV * HID: w_qkv = p; break;
            case N_QKV:       b_qkv = p; break;
            case HID * HID:   w_out = p; break;
            case HID:         b_out = p; break;
        }
    }
    float* out = (float*)d_out;

    __nv_bfloat16 *qkvh, *qkvl, *xs, *wqkvs, *atts, *wouts;
    cudaGetSymbolAddress((void**)&qkvh, g_qkvh);
    cudaGetSymbolAddress((void**)&qkvl, g_qkvl);
    cudaGetSymbolAddress((void**)&xs, g_xs);
    cudaGetSymbolAddress((void**)&wqkvs, g_wqkvs);
    cudaGetSymbolAddress((void**)&atts, g_atts);
    cudaGetSymbolAddress((void**)&wouts, g_wouts);

    cudaFuncSetAttribute(attn_tc,
                         cudaFuncAttributeMaxDynamicSharedMemorySize, ATT_SMEM);
    cudaFuncSetAttribute(gemm_hmma<true>,
                         cudaFuncAttributeMaxDynamicSharedMemorySize, GEMM_SMEM);
    cudaFuncSetAttribute(gemm_hmma<false>,
                         cudaFuncAttributeMaxDynamicSharedMemorySize, GEMM_SMEM);

    // Splits
    split_bf16<<<1024, 256>>>(x,     xs,    M_TOT, HID, 0);
    split_bf16<<<1024, 256>>>(w_qkv, wqkvs, N_QKV, HID, 1);
    split_bf16<<<1024, 256>>>(w_out, wouts, HID,   HID, 1);

    // GEMM1: qkv (bf16 hi/lo) = x @ w_qkv^T + b_qkv
    gemm_hmma<true><<<dim3(N_QKV / GBN, M_TOT / GBM), dim3(256), GEMM_SMEM>>>(
        xs, wqkvs, b_qkv, nullptr, qkvh, qkvl, M_TOT, N_QKV, K3);

    // Attention (tensor-core): writes augmented A for GEMM2
    attn_tc<<<dim3(SEQ / QROWS, BATCH * NHEAD), dim3(256), ATT_SMEM>>>(qkvh, qkvl, atts);

    // GEMM2: out = att @ w_out^T + b_out
    gemm_hmma<false><<<dim3(HID / GBN, M_TOT / GBM), dim3(256), GEMM_SMEM>>>(
        atts, wouts, b_out, out, nullptr, nullptr, M_TOT, HID, K3);
}

// round 12
// speedup vs baseline: 1.0930x; 1.0930x over previous
#include <cuda_runtime.h>
#include <cuda_bf16.h>
#include <cstdint>
#include <math.h>

#define HID 1024
#define NHEAD 16
#define HDIM 64
#define BATCH 2
#define SEQ 2048
#define M_TOT (BATCH * SEQ)     // 4096
#define N_QKV (3 * HID)         // 3072

// ---------------------------------------------------------------------------
// Scratch: separate hi/lo matrices (no augmented duplication)
// ---------------------------------------------------------------------------
__device__ __nv_bfloat16 g_qkvh[(size_t)M_TOT * N_QKV];     // 24 MB
__device__ __nv_bfloat16 g_qkvl[(size_t)M_TOT * N_QKV];     // 24 MB
__device__ __nv_bfloat16 g_xh[(size_t)M_TOT * HID];         // 8 MB
__device__ __nv_bfloat16 g_xl[(size_t)M_TOT * HID];         // 8 MB
__device__ __nv_bfloat16 g_wqh[(size_t)N_QKV * HID];        // 6 MB
__device__ __nv_bfloat16 g_wql[(size_t)N_QKV * HID];        // 6 MB
__device__ __nv_bfloat16 g_atth[(size_t)M_TOT * HID];       // 8 MB
__device__ __nv_bfloat16 g_attl[(size_t)M_TOT * HID];       // 8 MB
__device__ __nv_bfloat16 g_woh[(size_t)HID * HID];          // 2 MB
__device__ __nv_bfloat16 g_wol[(size_t)HID * HID];          // 2 MB

// ---------------------------------------------------------------------------
// Helpers
// ---------------------------------------------------------------------------
__device__ __forceinline__ uint32_t smem_u32(const void* p) {
    uint32_t a;
    asm("{ .reg .u64 t; cvta.to.shared.u64 t, %1; cvt.u32.u64 %0, t; }"
        : "=r"(a) : "l"(p));
    return a;
}
__device__ __forceinline__ void cp16(uint32_t dst, const void* src) {
    asm volatile("cp.async.cg.shared.global [%0], [%1], 16;" :: "r"(dst), "l"(src));
}
__device__ __forceinline__ void cp_commit() { asm volatile("cp.async.commit_group;"); }
template <int N>
__device__ __forceinline__ void cp_wait() { asm volatile("cp.async.wait_group %0;" :: "n"(N)); }

__device__ __forceinline__ void ldm_x4(uint32_t addr, uint32_t& r0, uint32_t& r1,
                                       uint32_t& r2, uint32_t& r3) {
    asm volatile("ldmatrix.sync.aligned.m8n8.x4.shared.b16 {%0,%1,%2,%3}, [%4];"
                 : "=r"(r0), "=r"(r1), "=r"(r2), "=r"(r3) : "r"(addr));
}
__device__ __forceinline__ void ldm_x4_t(uint32_t addr, uint32_t& r0, uint32_t& r1,
                                         uint32_t& r2, uint32_t& r3) {
    asm volatile("ldmatrix.sync.aligned.m8n8.x4.trans.shared.b16 {%0,%1,%2,%3}, [%4];"
                 : "=r"(r0), "=r"(r1), "=r"(r2), "=r"(r3) : "r"(addr));
}
__device__ __forceinline__ void mma_bf16(float* c, const uint32_t* a,
                                         uint32_t b0, uint32_t b1) {
    asm volatile(
        "mma.sync.aligned.m16n8k16.row.col.f32.bf16.bf16.f32 "
        "{%0,%1,%2,%3}, {%4,%5,%6,%7}, {%8,%9}, {%0,%1,%2,%3};"
        : "+f"(c[0]), "+f"(c[1]), "+f"(c[2]), "+f"(c[3])
        : "r"(a[0]), "r"(a[1]), "r"(a[2]), "r"(a[3]), "r"(b0), "r"(b1));
}
__device__ __forceinline__ uint32_t packbf(float a, float b) {
    __nv_bfloat162 t = __floats2bfloat162_rn(a, b);
    return *(uint32_t*)&t;
}
__device__ __forceinline__ uint32_t mulbf2(uint32_t x, uint32_t s) {
    __nv_bfloat162 r = __hmul2(*(__nv_bfloat162*)&x, *(__nv_bfloat162*)&s);
    return *(uint32_t*)&r;
}

// ---------------------------------------------------------------------------
// Split fp32 -> separate bf16 hi and lo matrices (row-major K, no dup)
// ---------------------------------------------------------------------------
__global__ void __launch_bounds__(256) split_pair(
    const float* __restrict__ in, __nv_bfloat16* __restrict__ oh,
    __nv_bfloat16* __restrict__ ol, int total_half)
{
    for (int i = blockIdx.x * blockDim.x + threadIdx.x; i < total_half;
         i += gridDim.x * blockDim.x) {
        float2 x = *(const float2*)(in + (size_t)i * 2);
        __nv_bfloat16 h0 = __float2bfloat16(x.x);
        __nv_bfloat16 h1 = __float2bfloat16(x.y);
        __nv_bfloat162 hh, ll;
        hh.x = h0; hh.y = h1;
        ll.x = __float2bfloat16(x.x - __bfloat162float(h0));
        ll.y = __float2bfloat16(x.y - __bfloat162float(h1));
        ((__nv_bfloat162*)oh)[i] = hh;
        ((__nv_bfloat162*)ol)[i] = ll;
    }
}

// ---------------------------------------------------------------------------
// HMMA bf16x3 NT GEMM, separate hi/lo operands (shared-fragment form):
// C = Ah·Bh^T + Ah·Bl^T + Al·Bh^T + bias. 128x128 CTA tile, 8 warps @ 64x32,
// K=1024, BK=64, 3-stage cp.async, frag ping-pong. 12 LDSM per 48 MMAs.
// ---------------------------------------------------------------------------
#define GBM 128
#define GBN 128
#define GBK 64
#define LDSK 72
#define GSTAGES 3
#define STG_T (GBM * LDSK * 2)             // 18432 B per tile
#define STG_QUAD (4 * STG_T)               // 73728 B per stage
#define GEMM_SMEM (GSTAGES * STG_QUAD)     // 221184 B

struct GFrag {
    uint32_t ah[4][4], al[4][4];
    uint32_t bh[2][4], bl[2][4];
};

template <bool BF16OUT>
__global__ void __launch_bounds__(256) gemm_hmma(
    const __nv_bfloat16* __restrict__ Ah, const __nv_bfloat16* __restrict__ Al,
    const __nv_bfloat16* __restrict__ Bh, const __nv_bfloat16* __restrict__ Bl,
    const float* __restrict__ bias, float* __restrict__ C,
    __nv_bfloat16* __restrict__ Ch, __nv_bfloat16* __restrict__ Cl,
    int M, int N, int K)
{
    extern __shared__ char gsm[];
    const uint32_t sbase = smem_u32(gsm);

    const int tid = threadIdx.x;
    const int wid = tid >> 5;
    const int lane = tid & 31;
    const int warp_m = (wid & 1) * 64;
    const int warp_n = (wid >> 1) * 32;
    const int m0 = blockIdx.y * GBM;
    const int n0 = blockIdx.x * GBN;

    const int ld_row = tid >> 3;       // 0..31
    const int ld_ch = (tid & 7) * 8;   // 0..56

    float acc[4][4][4];
#pragma unroll
    for (int i = 0; i < 4; i++)
#pragma unroll
        for (int j = 0; j < 4; j++)
#pragma unroll
            for (int q = 0; q < 4; q++) acc[i][j][q] = 0.f;

    const int NS = K / GBK;            // 16

    // stage layout: [Ah | Al | Bh | Bl], each GBM x LDSK
    auto load_stage = [&](int s, int p) {
        const int k0 = s * GBK;
        const uint32_t base = sbase + (uint32_t)p * STG_QUAD;
#pragma unroll
        for (int t = 0; t < 4; t++) {
            int row = ld_row + t * 32;
            uint32_t doff = (uint32_t)((row * LDSK + ld_ch) * 2);
            size_t ga = (size_t)(m0 + row) * K + k0 + ld_ch;
            size_t gb = (size_t)(n0 + row) * K + k0 + ld_ch;
            cp16(base + doff,              Ah + ga);
            cp16(base + STG_T + doff,      Al + ga);
            cp16(base + 2 * STG_T + doff,  Bh + gb);
            cp16(base + 3 * STG_T + doff,  Bl + gb);
        }
    };

    const int a_row = warp_m + (lane & 15);
    const int b_row = warp_n + (lane & 15);
    const int k_half = (lane >> 4) * 8;

    auto load_frags = [&](int p, int kk, GFrag& f) {
        const uint32_t base = sbase + (uint32_t)p * STG_QUAD;
        const int kc = kk * 16 + k_half;
#pragma unroll
        for (int i = 0; i < 4; i++) {
            uint32_t off = (uint32_t)(((a_row + i * 16) * LDSK + kc) * 2);
            ldm_x4(base + off,         f.ah[i][0], f.ah[i][1], f.ah[i][2], f.ah[i][3]);
            ldm_x4(base + STG_T + off, f.al[i][0], f.al[i][1], f.al[i][2], f.al[i][3]);
        }
#pragma unroll
        for (int jp = 0; jp < 2; jp++) {
            uint32_t off = (uint32_t)(((b_row + jp * 16) * LDSK + kc) * 2);
            ldm_x4(base + 2 * STG_T + off, f.bh[jp][0], f.bh[jp][1], f.bh[jp][2], f.bh[jp][3]);
            ldm_x4(base + 3 * STG_T + off, f.bl[jp][0], f.bl[jp][1], f.bl[jp][2], f.bl[jp][3]);
        }
    };

    // 48 MMAs per chunk: Ah·Bh, Ah·Bl, Al·Bh (grouped by term; 16 independent
    // accumulators between reuses of the same acc).
    auto mma_all = [&](GFrag& f) {
#pragma unroll
        for (int i = 0; i < 4; i++)
#pragma unroll
            for (int jp = 0; jp < 2; jp++) {
                mma_bf16(acc[i][2 * jp],     f.ah[i], f.bh[jp][0], f.bh[jp][2]);
                mma_bf16(acc[i][2 * jp + 1], f.ah[i], f.bh[jp][1], f.bh[jp][3]);
            }
#pragma unroll
        for (int i = 0; i < 4; i++)
#pragma unroll
            for (int jp = 0; jp < 2; jp++) {
                mma_bf16(acc[i][2 * jp],     f.ah[i], f.bl[jp][0], f.bl[jp][2]);
                mma_bf16(acc[i][2 * jp + 1], f.ah[i], f.bl[jp][1], f.bl[jp][3]);
            }
#pragma unroll
        for (int i = 0; i < 4; i++)
#pragma unroll
            for (int jp = 0; jp < 2; jp++) {
                mma_bf16(acc[i][2 * jp],     f.al[i], f.bh[jp][0], f.bh[jp][2]);
                mma_bf16(acc[i][2 * jp + 1], f.al[i], f.bh[jp][1], f.bh[jp][3]);
            }
    };

    // Prologue: 2 stages in flight
    load_stage(0, 0); cp_commit();
    load_stage(1, 1); cp_commit();
    cp_wait<1>();
    __syncthreads();

    GFrag fA, fB;
    load_frags(0, 0, fA);

    int p = 0, pn = 2;
    for (int s = 0; s < NS; s++) {
        { int ns = s + 2; if (ns < NS) load_stage(ns, pn); cp_commit(); }

        load_frags(p, 1, fB); mma_all(fA);
        load_frags(p, 2, fA); mma_all(fB);
        load_frags(p, 3, fB); mma_all(fA);
        mma_all(fB);

        cp_wait<1>();
        __syncthreads();
        p  = (p == 2)  ? 0 : p + 1;
        pn = (pn == 2) ? 0 : pn + 1;
        if (s + 1 < NS) load_frags(p, 0, fA);
    }

    const int row_g = lane >> 2;
    const int col_g = (lane & 3) * 2;
#pragma unroll
    for (int i = 0; i < 4; i++) {
#pragma unroll
        for (int j = 0; j < 4; j++) {
            int row = m0 + warp_m + i * 16 + row_g;
            int col = n0 + warp_n + j * 8 + col_g;
            float b0 = bias[col], b1 = bias[col + 1];
            float v00 = acc[i][j][0] + b0, v01 = acc[i][j][1] + b1;
            float v10 = acc[i][j][2] + b0, v11 = acc[i][j][3] + b1;
            if (BF16OUT) {
                __nv_bfloat162 h0 = __floats2bfloat162_rn(v00, v01);
                __nv_bfloat162 h1 = __floats2bfloat162_rn(v10, v11);
                __nv_bfloat162 l0 = __floats2bfloat162_rn(
                    v00 - __bfloat162float(h0.x), v01 - __bfloat162float(h0.y));
                __nv_bfloat162 l1 = __floats2bfloat162_rn(
                    v10 - __bfloat162float(h1.x), v11 - __bfloat162float(h1.y));
                *(__nv_bfloat162*)(Ch + (size_t)row * N + col) = h0;
                *(__nv_bfloat162*)(Ch + (size_t)(row + 8) * N + col) = h1;
                *(__nv_bfloat162*)(Cl + (size_t)row * N + col) = l0;
                *(__nv_bfloat162*)(Cl + (size_t)(row + 8) * N + col) = l1;
            } else {
                *(float2*)(C + (size_t)row * N + col) = make_float2(v00, v01);
                *(float2*)(C + (size_t)(row + 8) * N + col) = make_float2(v10, v11);
            }
        }
    }
}

// ---------------------------------------------------------------------------
// Tensor-core flash attention (R10 config: 64 q-rows, 128 threads).
// Max-free softmax; epilogue writes separate hi/lo matrices for GEMM2.
// ---------------------------------------------------------------------------
#define APITCH 72
#define ATILE (64 * APITCH)                 // elems per tile
#define ATT_SMEM ((2 + 8) * ATILE * 2)      // 92160 B

__global__ void __launch_bounds__(128) attn_tc(
    const __nv_bfloat16* __restrict__ qh, const __nv_bfloat16* __restrict__ ql,
    __nv_bfloat16* __restrict__ atth, __nv_bfloat16* __restrict__ attl)
{
    extern __shared__ __nv_bfloat16 sm[];
    __nv_bfloat16* Qh = sm;
    __nv_bfloat16* Ql = Qh + ATILE;
    __nv_bfloat16* KV = Ql + ATILE;      // stage p: [Kh, Kl, Vh, Vl] each ATILE

    const int tid = threadIdx.x;
    const int wid = tid >> 5;
    const int lane = tid & 31;
    const int bh = blockIdx.y;
    const int b = bh >> 4, h = bh & 15;
    const int q0 = blockIdx.x * 64;
    const size_t tokbase = (size_t)b * SEQ;

    const uint32_t sQh = smem_u32(Qh), sQl = smem_u32(Ql);
    const uint32_t sKV = smem_u32(KV);

    // Load Q tile (hi, lo)
    {
        const size_t qoff = (tokbase + q0) * N_QKV + h * HDIM;
#pragma unroll
        for (int t = 0; t < 4; t++) {
            int idx = tid + t * 128;
            int row = idx >> 3;
            int ch = (idx & 7) * 8;
            *(uint4*)(Qh + row * APITCH + ch) = *(const uint4*)(qh + qoff + (size_t)row * N_QKV + ch);
            *(uint4*)(Ql + row * APITCH + ch) = *(const uint4*)(ql + qoff + (size_t)row * N_QKV + ch);
        }
    }

    auto load_kv = [&](int kt, int p) {
        const size_t koff = (tokbase + kt * 64) * N_QKV + HID + h * HDIM;
        const size_t voff = koff + HID;
        const uint32_t base = sKV + (uint32_t)p * (4 * ATILE * 2);
#pragma unroll
        for (int t = 0; t < 4; t++) {
            int idx = tid + t * 128;
            int row = idx >> 3;
            int ch = (idx & 7) * 8;
            size_t g = (size_t)row * N_QKV + ch;
            uint32_t doff = (uint32_t)((row * APITCH + ch) * 2);
            cp16(base + doff,                 qh + koff + g);
            cp16(base + ATILE * 2 + doff,     ql + koff + g);
            cp16(base + 2 * ATILE * 2 + doff, qh + voff + g);
            cp16(base + 3 * ATILE * 2 + doff, ql + voff + g);
        }
    };

    load_kv(0, 0);
    cp_commit();
    __syncthreads();   // Q stores visible

    const int lrow = lane & 15;
    const int lkh = (lane >> 4) * 8;
    const int vkey = (lane >> 4) * 8 + (lane & 7);
    const int vd = ((lane >> 3) & 1) * 8;

    // Hoist Q fragments (hi, lo), pre-scaled by 1/8 (exact in bf16)
    const uint32_t SC = 0x3E003E00u;   // (0.125, 0.125) bf16x2
    uint32_t qfh[4][4], qfl[4][4];
#pragma unroll
    for (int kk = 0; kk < 4; kk++) {
        const uint32_t qoff2 = (uint32_t)(((wid * 16 + lrow) * APITCH + kk * 16 + lkh) * 2);
        ldm_x4(sQh + qoff2, qfh[kk][0], qfh[kk][1], qfh[kk][2], qfh[kk][3]);
        ldm_x4(sQl + qoff2, qfl[kk][0], qfl[kk][1], qfl[kk][2], qfl[kk][3]);
#pragma unroll
        for (int r = 0; r < 4; r++) {
            qfh[kk][r] = mulbf2(qfh[kk][r], SC);
            qfl[kk][r] = mulbf2(qfl[kk][r], SC);
        }
    }

    float l0 = 0.f, l1 = 0.f;
    float o[8][4];
#pragma unroll
    for (int t = 0; t < 8; t++)
#pragma unroll
        for (int q = 0; q < 4; q++) o[t][q] = 0.f;

    const int NK = SEQ / 64;
    for (int kt = 0; kt < NK; kt++) {
        const int p = kt & 1;
        cp_wait<0>();
        __syncthreads();
        if (kt + 1 < NK) load_kv(kt + 1, p ^ 1);
        cp_commit();

        const uint32_t base = sKV + (uint32_t)p * (4 * ATILE * 2);
        const uint32_t sKh = base;
        const uint32_t sKl = base + ATILE * 2;
        const uint32_t sVh = base + 2 * ATILE * 2;
        const uint32_t sVl = base + 3 * ATILE * 2;

        auto load_kfrags = [&](int kk, uint32_t (&kh)[4][4], uint32_t (&kl)[4][4]) {
#pragma unroll
            for (int jp = 0; jp < 4; jp++) {
                const uint32_t koff2 = (uint32_t)(((jp * 16 + lrow) * APITCH + kk * 16 + lkh) * 2);
                ldm_x4(sKh + koff2, kh[jp][0], kh[jp][1], kh[jp][2], kh[jp][3]);
                ldm_x4(sKl + koff2, kl[jp][0], kl[jp][1], kl[jp][2], kl[jp][3]);
            }
        };
        auto load_vfrags = [&](int kk, uint32_t (&vh)[4][4], uint32_t (&vl)[4][4]) {
#pragma unroll
            for (int dt = 0; dt < 4; dt++) {
                const uint32_t voff2 = (uint32_t)(((kk * 16 + vkey) * APITCH + dt * 16 + vd) * 2);
                ldm_x4_t(sVh + voff2, vh[dt][0], vh[dt][1], vh[dt][2], vh[dt][3]);
                ldm_x4_t(sVl + voff2, vl[dt][0], vl[dt][1], vl[dt][2], vl[dt][3]);
            }
        };

        // ---- S = Q K^T (3-term split); grouped by term, frag ping-pong ----
        float sf[8][4];
#pragma unroll
        for (int t = 0; t < 8; t++)
#pragma unroll
            for (int q = 0; q < 4; q++) sf[t][q] = 0.f;

        auto s_mma = [&](int kk, uint32_t (&kh)[4][4], uint32_t (&kl)[4][4]) {
#pragma unroll
            for (int jp = 0; jp < 4; jp++) {
                mma_bf16(sf[2 * jp],     qfh[kk], kh[jp][0], kh[jp][2]);
                mma_bf16(sf[2 * jp + 1], qfh[kk], kh[jp][1], kh[jp][3]);
            }
#pragma unroll
            for (int jp = 0; jp < 4; jp++) {
                mma_bf16(sf[2 * jp],     qfh[kk], kl[jp][0], kl[jp][2]);
                mma_bf16(sf[2 * jp + 1], qfh[kk], kl[jp][1], kl[jp][3]);
            }
#pragma unroll
            for (int jp = 0; jp < 4; jp++) {
                mma_bf16(sf[2 * jp],     qfl[kk], kh[jp][0], kh[jp][2]);
                mma_bf16(sf[2 * jp + 1], qfl[kk], kh[jp][1], kh[jp][3]);
            }
        };

        {
            uint32_t khA[4][4], klA[4][4], khB[4][4], klB[4][4];
            load_kfrags(0, khA, klA);
            load_kfrags(1, khB, klB); s_mma(0, khA, klA);
            load_kfrags(2, khA, klA); s_mma(1, khB, klB);
            load_kfrags(3, khB, klB); s_mma(2, khA, klA);
            s_mma(3, khB, klB);
        }

        // ---- V(kk=0) frags issued before exp to hide LDSM latency ----
        uint32_t vhA[4][4], vlA[4][4], vhB[4][4], vlB[4][4];
        load_vfrags(0, vhA, vlA);

        // ---- max-free softmax: P = exp(S), accumulate row sums per lane ----
#pragma unroll
        for (int t = 0; t < 8; t++) {
            sf[t][0] = __expf(sf[t][0]);
            sf[t][1] = __expf(sf[t][1]);
            sf[t][2] = __expf(sf[t][2]);
            sf[t][3] = __expf(sf[t][3]);
            l0 += sf[t][0] + sf[t][1];
            l1 += sf[t][2] + sf[t][3];
        }

        // ---- pack P into A-operand frags (hi + lo) ----
        uint32_t ph[4][4], pl[4][4];
#pragma unroll
        for (int kk = 0; kk < 4; kk++) {
            float* c0 = sf[2 * kk];
            float* c1 = sf[2 * kk + 1];
            ph[kk][0] = packbf(c0[0], c0[1]);
            ph[kk][1] = packbf(c0[2], c0[3]);
            ph[kk][2] = packbf(c1[0], c1[1]);
            ph[kk][3] = packbf(c1[2], c1[3]);
            __nv_bfloat162* hp;
            hp = (__nv_bfloat162*)&ph[kk][0];
            pl[kk][0] = packbf(c0[0] - __bfloat162float(hp->x), c0[1] - __bfloat162float(hp->y));
            hp = (__nv_bfloat162*)&ph[kk][1];
            pl[kk][1] = packbf(c0[2] - __bfloat162float(hp->x), c0[3] - __bfloat162float(hp->y));
            hp = (__nv_bfloat162*)&ph[kk][2];
            pl[kk][2] = packbf(c1[0] - __bfloat162float(hp->x), c1[1] - __bfloat162float(hp->y));
            hp = (__nv_bfloat162*)&ph[kk][3];
            pl[kk][3] = packbf(c1[2] - __bfloat162float(hp->x), c1[3] - __bfloat162float(hp->y));
        }

        // ---- O += P V (3-term split); grouped by term, frag ping-pong ----
        auto pv_mma = [&](int kk, uint32_t (&vh)[4][4], uint32_t (&vl)[4][4]) {
#pragma unroll
            for (int dt = 0; dt < 4; dt++) {
                mma_bf16(o[2 * dt],     ph[kk], vh[dt][0], vh[dt][2]);
                mma_bf16(o[2 * dt + 1], ph[kk], vh[dt][1], vh[dt][3]);
            }
#pragma unroll
            for (int dt = 0; dt < 4; dt++) {
                mma_bf16(o[2 * dt],     ph[kk], vl[dt][0], vl[dt][2]);
                mma_bf16(o[2 * dt + 1], ph[kk], vl[dt][1], vl[dt][3]);
            }
#pragma unroll
            for (int dt = 0; dt < 4; dt++) {
                mma_bf16(o[2 * dt],     pl[kk], vh[dt][0], vh[dt][2]);
                mma_bf16(o[2 * dt + 1], pl[kk], vh[dt][1], vh[dt][3]);
            }
        };

        load_vfrags(1, vhB, vlB); pv_mma(0, vhA, vlA);
        load_vfrags(2, vhA, vlA); pv_mma(1, vhB, vlB);
        load_vfrags(3, vhB, vlB); pv_mma(2, vhA, vlA);
        pv_mma(3, vhB, vlB);
    }

    // ---- one-time cross-lane row-sum reduction (quad lanes share a row) ----
    l0 += __shfl_xor_sync(0xffffffffu, l0, 1);
    l0 += __shfl_xor_sync(0xffffffffu, l0, 2);
    l1 += __shfl_xor_sync(0xffffffffu, l1, 1);
    l1 += __shfl_xor_sync(0xffffffffu, l1, 2);

    // ---- epilogue: write hi/lo matrices for GEMM2 ----
    const float inv0 = 1.f / l0, inv1 = 1.f / l1;
    const int gr0 = q0 + wid * 16 + (lane >> 2);
    const int gr1 = gr0 + 8;
    const size_t r0base = (tokbase + gr0) * (size_t)HID;
    const size_t r1base = (tokbase + gr1) * (size_t)HID;
#pragma unroll
    for (int t = 0; t < 8; t++) {
        int col = h * HDIM + t * 8 + (lane & 3) * 2;
        float v00 = o[t][0] * inv0, v01 = o[t][1] * inv0;
        float v10 = o[t][2] * inv1, v11 = o[t][3] * inv1;
        __nv_bfloat162 h0 = __floats2bfloat162_rn(v00, v01);
        __nv_bfloat162 h1 = __floats2bfloat162_rn(v10, v11);
        __nv_bfloat162 lo0 = __floats2bfloat162_rn(v00 - __bfloat162float(h0.x),
                                                   v01 - __bfloat162float(h0.y));
        __nv_bfloat162 lo1 = __floats2bfloat162_rn(v10 - __bfloat162float(h1.x),
                                                   v11 - __bfloat162float(h1.y));
        *(__nv_bfloat162*)(atth + r0base + col) = h0;
        *(__nv_bfloat162*)(attl + r0base + col) = lo0;
        *(__nv_bfloat162*)(atth + r1base + col) = h1;
        *(__nv_bfloat162*)(attl + r1base + col) = lo1;
    }
}

// ---------------------------------------------------------------------------
// Launch
// ---------------------------------------------------------------------------
extern "C" void kernel_launch(void* const* d_in, const int* in_sizes, int n_in,
                              void* d_out, int out_size)
{
    const float *x = nullptr, *w_qkv = nullptr, *b_qkv = nullptr,
                *w_out = nullptr, *b_out = nullptr;
    for (int i = 0; i < n_in; i++) {
        const float* p = (const float*)d_in[i];
        switch (in_sizes[i]) {
            case M_TOT * HID: x = p; break;
            case N_QKV * HID: w_qkv = p; break;
            case N_QKV:       b_qkv = p; break;
            case HID * HID:   w_out = p; break;
            case HID:         b_out = p; break;
        }
    }
    float* out = (float*)d_out;

    __nv_bfloat16 *qkvh, *qkvl, *xh, *xl, *wqh, *wql, *atth, *attl, *woh, *wol;
    cudaGetSymbolAddress((void**)&qkvh, g_qkvh);
    cudaGetSymbolAddress((void**)&qkvl, g_qkvl);
    cudaGetSymbolAddress((void**)&xh, g_xh);
    cudaGetSymbolAddress((void**)&xl, g_xl);
    cudaGetSymbolAddress((void**)&wqh, g_wqh);
    cudaGetSymbolAddress((void**)&wql, g_wql);
    cudaGetSymbolAddress((void**)&atth, g_atth);
    cudaGetSymbolAddress((void**)&attl, g_attl);
    cudaGetSymbolAddress((void**)&woh, g_woh);
    cudaGetSymbolAddress((void**)&wol, g_wol);

    cudaFuncSetAttribute(attn_tc,
                         cudaFuncAttributeMaxDynamicSharedMemorySize, ATT_SMEM);
    cudaFuncSetAttribute(gemm_hmma<true>,
                         cudaFuncAttributeMaxDynamicSharedMemorySize, GEMM_SMEM);
    cudaFuncSetAttribute(gemm_hmma<false>,
                         cudaFuncAttributeMaxDynamicSharedMemorySize, GEMM_SMEM);

    // Splits (hi/lo pairs, no duplication)
    split_pair<<<512, 256>>>(x,     xh,  xl,  M_TOT * HID / 2);
    split_pair<<<512, 256>>>(w_qkv, wqh, wql, N_QKV * HID / 2);
    split_pair<<<256, 256>>>(w_out, woh, wol, HID * HID / 2);

    // GEMM1: qkv (bf16 hi/lo) = x @ w_qkv^T + b_qkv   (K = 1024)
    gemm_hmma<true><<<dim3(N_QKV / GBN, M_TOT / GBM), dim3(256), GEMM_SMEM>>>(
        xh, xl, wqh, wql, b_qkv, nullptr, qkvh, qkvl, M_TOT, N_QKV, HID);

    // Attention: writes hi/lo A matrices for GEMM2
    attn_tc<<<dim3(SEQ / 64, BATCH * NHEAD), dim3(128), ATT_SMEM>>>(
        qkvh, qkvl, atth, attl);

    // GEMM2: out = att @ w_out^T + b_out   (K = 1024)
    gemm_hmma<false><<<dim3(HID / GBN, M_TOT / GBM), dim3(256), GEMM_SMEM>>>(
        atth, attl, woh, wol, b_out, out, nullptr, nullptr, M_TOT, HID, HID);
}